// round 4
// baseline (speedup 1.0000x reference)
#include <cuda_runtime.h>
#include <cuda_fp16.h>
#include <mma.h>
#include <cstdint>

using namespace nvcuda;

#define THREADS 256
#define M_AG 64   // agents per CTA tile

// ---- SMEM byte offsets ----
enum {
  O_WA_HI  = 0,        // [64][128] fp16
  O_WA_LO  = 16384,
  O_WNH_HI = 32768,    // [64][256] fp16 (cols 0-127 Wn, 128-255 Wh)
  O_WNH_LO = 65536,
  O_WO_HI  = 98304,    // [128][64] fp16
  O_WO_LO  = 114688,
  O_A      = 131072,   // f32 [64][128]; reused as GEMM3 out staging [64][64]
  O_H_HI   = 163840,   // fp16 [64][128]
  O_H_LO   = 180224,
  O_X_HI   = 163840,   // overlaps H_HI (X dead before H written)
  O_X_LO   = 172032,
  O_NBR_HI = 196608,   // fp16 [64][64] neighbor chunk
  O_NBR_LO = 204800,
  O_SCR    = 212992,   // 8 warps * [16][32] f32
  O_BA     = 229376,   // f32[128]
  O_BN     = 229888,
  O_BH     = 230400,
  O_BO     = 230912,   // f32[64]
  O_MSK    = 231168,   // f32[256]
  SMEM_TOTAL = 232192
};

typedef wmma::fragment<wmma::matrix_a, 16, 16, 16, __half, wmma::row_major> frag_a;
typedef wmma::fragment<wmma::matrix_b, 16, 16, 16, __half, wmma::row_major> frag_b;
typedef wmma::fragment<wmma::accumulator, 16, 16, 16, float> frag_c;

__device__ __forceinline__ void split16(float x, __half& hi, __half& lo) {
    hi = __float2half_rn(x);
    lo = __float2half_rn(x - __half2float(hi));
}

__global__ __launch_bounds__(THREADS, 1)
void gat_wmma(const float* __restrict__ agent,
              const float* __restrict__ neighbor,
              const int*   __restrict__ nmask,
              const float* __restrict__ Wa, const float* __restrict__ ba,
              const float* __restrict__ Wn, const float* __restrict__ bn,
              const float* __restrict__ Wh, const float* __restrict__ bh,
              const float* __restrict__ Wo, const float* __restrict__ bo,
              float* __restrict__ out, int n, int ntiles)
{
    extern __shared__ char sm[];
    __half* wa_hi  = (__half*)(sm + O_WA_HI);
    __half* wa_lo  = (__half*)(sm + O_WA_LO);
    __half* wnh_hi = (__half*)(sm + O_WNH_HI);
    __half* wnh_lo = (__half*)(sm + O_WNH_LO);
    __half* wo_hi  = (__half*)(sm + O_WO_HI);
    __half* wo_lo  = (__half*)(sm + O_WO_LO);
    float*  A      = (float*)(sm + O_A);
    __half* Hh     = (__half*)(sm + O_H_HI);
    __half* Hl     = (__half*)(sm + O_H_LO);
    __half* xh     = (__half*)(sm + O_X_HI);
    __half* xl     = (__half*)(sm + O_X_LO);
    __half* nbh    = (__half*)(sm + O_NBR_HI);
    __half* nbl    = (__half*)(sm + O_NBR_LO);
    float*  sba    = (float*)(sm + O_BA);
    float*  sbn    = (float*)(sm + O_BN);
    float*  sbh    = (float*)(sm + O_BH);
    float*  sbo    = (float*)(sm + O_BO);
    float*  msk    = (float*)(sm + O_MSK);

    const int tid  = threadIdx.x;
    const int lane = tid & 31;
    const int w    = tid >> 5;
    float* scr = (float*)(sm + O_SCR) + w * 512;   // [16][32] per warp

    // ---- once: weights (hi/lo fp16 split) + biases ----
    for (int i = tid; i < 64 * 128; i += THREADS)
        split16(Wa[i], wa_hi[i], wa_lo[i]);
    for (int i = tid; i < 64 * 256; i += THREADS) {
        int k = i >> 8, c = i & 255;
        float x = (c < 128) ? Wn[k * 128 + c] : Wh[k * 128 + c - 128];
        split16(x, wnh_hi[i], wnh_lo[i]);
    }
    for (int i = tid; i < 128 * 64; i += THREADS)
        split16(Wo[i], wo_hi[i], wo_lo[i]);
    if (tid < 128) {
        sba[tid] = ba[tid];
        sbn[tid] = bn[tid];
        sbh[tid] = bh[tid];
        if (tid < 64) sbo[tid] = bo[tid];
    }
    __syncthreads();

    for (int tile = blockIdx.x; tile < ntiles; tile += gridDim.x) {
        const int base = tile * M_AG;

        // ---- X (agents) + masks ----
        for (int i = tid; i < 64 * 64; i += THREADS) {
            int r = i >> 6, c = i & 63;
            int ag = min(base + r, n - 1);
            split16(agent[(size_t)ag * 64 + c], xh[i], xl[i]);
        }
        {
            int a = tid >> 2;
            int ag = min(base + a, n - 1);
            msk[tid] = (float)nmask[(size_t)ag * 4 + (tid & 3)];
        }
        __syncthreads();

        // ---- GEMM1: A = X @ Wa  (64x128, K=64, 3-way split) ----
        for (int t = w; t < 32; t += 8) {
            int rb = t >> 3, nb = t & 7;
            frag_c acc;
            wmma::fill_fragment(acc, 0.f);
#pragma unroll
            for (int k = 0; k < 4; ++k) {
                frag_a ahf, alf;
                frag_b bhf, blf;
                wmma::load_matrix_sync(ahf, xh + rb * 16 * 64 + k * 16, 64);
                wmma::load_matrix_sync(alf, xl + rb * 16 * 64 + k * 16, 64);
                wmma::load_matrix_sync(bhf, wa_hi + k * 16 * 128 + nb * 16, 128);
                wmma::load_matrix_sync(blf, wa_lo + k * 16 * 128 + nb * 16, 128);
                wmma::mma_sync(acc, ahf, bhf, acc);
                wmma::mma_sync(acc, ahf, blf, acc);
                wmma::mma_sync(acc, alf, bhf, acc);
            }
            wmma::store_matrix_sync(A + rb * 16 * 128 + nb * 16, acc, 128,
                                    wmma::mem_row_major);
        }
        __syncthreads();
        for (int i = tid; i < 64 * 128; i += THREADS)
            A[i] = fmaxf(A[i] + sba[i & 127], 0.f);
        __syncthreads();

        // ---- neighbor chunks: 4 x (16 agents = 64 rows) ----
        for (int c = 0; c < 4; ++c) {
            for (int i = tid; i < 64 * 64; i += THREADS) {
                int r = i >> 6, cc = i & 63;
                int ag = min(base + c * 16 + (r >> 2), n - 1);
                float x = neighbor[((size_t)ag * 4 + (r & 3)) * 64 + cc];
                split16(x, nbh[i], nbl[i]);
            }
            __syncthreads();

#pragma unroll
            for (int pi = 0; pi < 2; ++pi) {
                const int p  = w + pi * 8;
                const int rb = p >> 2, h = p & 3;

                // nr = NBR @ Wn[:, h*32 : h*32+32]
                {
                    frag_c acc[2];
                    wmma::fill_fragment(acc[0], 0.f);
                    wmma::fill_fragment(acc[1], 0.f);
#pragma unroll
                    for (int k = 0; k < 4; ++k) {
                        frag_a ahf, alf;
                        wmma::load_matrix_sync(ahf, nbh + rb * 16 * 64 + k * 16, 64);
                        wmma::load_matrix_sync(alf, nbl + rb * 16 * 64 + k * 16, 64);
#pragma unroll
                        for (int nt = 0; nt < 2; ++nt) {
                            frag_b bhf, blf;
                            wmma::load_matrix_sync(bhf,
                                wnh_hi + k * 16 * 256 + h * 32 + nt * 16, 256);
                            wmma::load_matrix_sync(blf,
                                wnh_lo + k * 16 * 256 + h * 32 + nt * 16, 256);
                            wmma::mma_sync(acc[nt], ahf, bhf, acc[nt]);
                            wmma::mma_sync(acc[nt], ahf, blf, acc[nt]);
                            wmma::mma_sync(acc[nt], alf, bhf, acc[nt]);
                        }
                    }
                    wmma::store_matrix_sync(scr, acc[0], 32, wmma::mem_row_major);
                    wmma::store_matrix_sync(scr + 16, acc[1], 32, wmma::mem_row_major);
                }
                __syncwarp();

                // attention dot + softmax (rows duplicated across warp halves)
                const int rl  = lane & 15;
                const int a_c = rb * 4 + (rl >> 2);
                const int nbr = rl & 3;
                const int a_t = c * 16 + a_c;
                float pdot = 0.f;
                {
                    const float* arow  = A + a_t * 128 + h * 32;
                    const float* bnrow = sbn + h * 32;
#pragma unroll
                    for (int m = 0; m < 32; ++m)
                        pdot = fmaf(fmaxf(scr[rl * 32 + m] + bnrow[m], 0.f),
                                    arow[m], pdot);
                }
                float mk = msk[a_t * 4 + nbr];
                float lg = fmaf(mk, -1e8f, pdot);
                float mx = lg;
                mx = fmaxf(mx, __shfl_xor_sync(0xffffffffu, mx, 1));
                mx = fmaxf(mx, __shfl_xor_sync(0xffffffffu, mx, 2));
                float e = __expf(lg - mx);
                float s = e;
                s += __shfl_xor_sync(0xffffffffu, s, 1);
                s += __shfl_xor_sync(0xffffffffu, s, 2);
                float sc = (1.f - mk) * e * 0.25f / s;
                __syncwarp();

                // nh = NBR @ Wh[:, h*32 : h*32+32]
                {
                    frag_c acc[2];
                    wmma::fill_fragment(acc[0], 0.f);
                    wmma::fill_fragment(acc[1], 0.f);
#pragma unroll
                    for (int k = 0; k < 4; ++k) {
                        frag_a ahf, alf;
                        wmma::load_matrix_sync(ahf, nbh + rb * 16 * 64 + k * 16, 64);
                        wmma::load_matrix_sync(alf, nbl + rb * 16 * 64 + k * 16, 64);
#pragma unroll
                        for (int nt = 0; nt < 2; ++nt) {
                            frag_b bhf, blf;
                            wmma::load_matrix_sync(bhf,
                                wnh_hi + k * 16 * 256 + 128 + h * 32 + nt * 16, 256);
                            wmma::load_matrix_sync(blf,
                                wnh_lo + k * 16 * 256 + 128 + h * 32 + nt * 16, 256);
                            wmma::mma_sync(acc[nt], ahf, bhf, acc[nt]);
                            wmma::mma_sync(acc[nt], ahf, blf, acc[nt]);
                            wmma::mma_sync(acc[nt], alf, bhf, acc[nt]);
                        }
                    }
                    wmma::store_matrix_sync(scr, acc[0], 32, wmma::mem_row_major);
                    wmma::store_matrix_sync(scr + 16, acc[1], 32, wmma::mem_row_major);
                }
                __syncwarp();

                // H[agent, h*32+m] = sum_nbr score * relu(nh + bh)
                {
                    const int m = lane;
                    const float bhv = sbh[h * 32 + m];
#pragma unroll
                    for (int q = 0; q < 4; ++q) {
                        float s0 = __shfl_sync(0xffffffffu, sc, q * 4 + 0);
                        float s1 = __shfl_sync(0xffffffffu, sc, q * 4 + 1);
                        float s2 = __shfl_sync(0xffffffffu, sc, q * 4 + 2);
                        float s3 = __shfl_sync(0xffffffffu, sc, q * 4 + 3);
                        float v =
                            s0 * fmaxf(scr[(q * 4 + 0) * 32 + m] + bhv, 0.f) +
                            s1 * fmaxf(scr[(q * 4 + 1) * 32 + m] + bhv, 0.f) +
                            s2 * fmaxf(scr[(q * 4 + 2) * 32 + m] + bhv, 0.f) +
                            s3 * fmaxf(scr[(q * 4 + 3) * 32 + m] + bhv, 0.f);
                        int hr = c * 16 + rb * 4 + q;
                        __half vh, vl;
                        split16(v, vh, vl);
                        Hh[hr * 128 + h * 32 + m] = vh;
                        Hl[hr * 128 + h * 32 + m] = vl;
                    }
                }
                __syncwarp();
            }
            __syncthreads();
        }

        // ---- GEMM3: out = H @ Wo  (64x64, K=128, 3-way split) ----
        for (int t = w; t < 16; t += 8) {
            int rb = t >> 2, nb = t & 3;
            frag_c acc;
            wmma::fill_fragment(acc, 0.f);
#pragma unroll
            for (int k = 0; k < 8; ++k) {
                frag_a ahf, alf;
                frag_b bhf, blf;
                wmma::load_matrix_sync(ahf, Hh + rb * 16 * 128 + k * 16, 128);
                wmma::load_matrix_sync(alf, Hl + rb * 16 * 128 + k * 16, 128);
                wmma::load_matrix_sync(bhf, wo_hi + k * 16 * 64 + nb * 16, 64);
                wmma::load_matrix_sync(blf, wo_lo + k * 16 * 64 + nb * 16, 64);
                wmma::mma_sync(acc, ahf, bhf, acc);
                wmma::mma_sync(acc, ahf, blf, acc);
                wmma::mma_sync(acc, alf, bhf, acc);
            }
            wmma::store_matrix_sync(A + rb * 16 * 64 + nb * 16, acc, 64,
                                    wmma::mem_row_major);
        }
        __syncthreads();
        for (int i = tid; i < 64 * 64; i += THREADS) {
            int r = i >> 6, cc = i & 63;
            int ag = base + r;
            if (ag < n)
                out[(size_t)ag * 64 + cc] = fmaxf(A[i] + sbo[cc], 0.f);
        }
        __syncthreads();
    }
}

extern "C" void kernel_launch(void* const* d_in, const int* in_sizes, int n_in,
                              void* d_out, int out_size)
{
    const float* agent    = (const float*)d_in[0];
    const float* neighbor = (const float*)d_in[1];
    const int*   nmask    = (const int*)d_in[2];
    const float* Wa       = (const float*)d_in[3];
    const float* ba       = (const float*)d_in[4];
    const float* Wn       = (const float*)d_in[5];
    const float* bn       = (const float*)d_in[6];
    const float* Wh       = (const float*)d_in[7];
    const float* bh       = (const float*)d_in[8];
    const float* Wo       = (const float*)d_in[9];
    const float* bo       = (const float*)d_in[10];
    float* out = (float*)d_out;

    const int n = in_sizes[0] / 64;
    const int ntiles = (n + M_AG - 1) / M_AG;

    cudaFuncSetAttribute(gat_wmma, cudaFuncAttributeMaxDynamicSharedMemorySize,
                         SMEM_TOTAL);

    int sms = 148;
    cudaDeviceGetAttribute(&sms, cudaDevAttrMultiProcessorCount, 0);
    int grid = sms < ntiles ? sms : ntiles;
    if (grid < 1) grid = 1;

    gat_wmma<<<grid, THREADS, SMEM_TOTAL>>>(agent, neighbor, nmask,
                                            Wa, ba, Wn, bn, Wh, bh, Wo, bo,
                                            out, n, ntiles);
}

// round 5
// speedup vs baseline: 4.0356x; 4.0356x over previous
#include <cuda_runtime.h>
#include <cuda_fp16.h>
#include <mma.h>
#include <cstdint>

using namespace nvcuda;

#define THREADS 256
#define M_AG 64          // agents per CTA tile
#define CHUNK_AG 4       // agents per neighbor chunk
#define NCHUNK 16

// padded leading dimensions (halfs / floats); pad so row stride % 128B == 16B
#define LD_X    72
#define LD_WA   136
#define LD_WNH  264
#define LD_WO   72
#define LD_H    136
#define LD_A    132
#define LD_NR   264
#define LD_O    68

enum {
  O_WA_HI  = 0,                       // [64][136] fp16
  O_WA_LO  = 17408,
  O_WNH_HI = 34816,                   // [64][264] fp16  (Wn | Wh)
  O_WNH_LO = 68608,
  O_WO_HI  = 102400,                  // [128][72] fp16
  O_WO_LO  = 120832,
  O_H_HI   = 139264,                  // [64][136] fp16
  O_H_LO   = 156672,
  O_X_HI   = 139264,                  // [64][72] overlays H (X dead before H written)
  O_X_LO   = 148480,
  O_A      = 174080,                  // f32 [64][132]; reused as out stage [64][68]
  O_NRNH   = 207872,                  // f32 [16][264] chunk (nr cols 0-127, nh 128-255)
  O_NBR_HI = 224768,                  // [16][72] fp16 chunk
  O_NBR_LO = 227072,
  O_BA     = 229376,                  // f32[128]
  O_BO     = 229888,                  // f32[64]
  O_MSK    = 230144,                  // f32[256]
  SMEM_TOTAL = 231168
};

typedef wmma::fragment<wmma::matrix_a, 16, 16, 16, __half, wmma::row_major> frag_a;
typedef wmma::fragment<wmma::matrix_b, 16, 16, 16, __half, wmma::row_major> frag_b;
typedef wmma::fragment<wmma::accumulator, 16, 16, 16, float> frag_c;

__device__ __forceinline__ void split16(float x, __half& hi, __half& lo) {
    hi = __float2half_rn(x);
    lo = __float2half_rn(x - __half2float(hi));
}

__global__ __launch_bounds__(THREADS, 1)
void gat_wmma2(const float* __restrict__ agent,
               const float* __restrict__ neighbor,
               const int*   __restrict__ nmask,
               const float* __restrict__ Wa, const float* __restrict__ ba,
               const float* __restrict__ Wn, const float* __restrict__ bn,
               const float* __restrict__ Wh, const float* __restrict__ bh,
               const float* __restrict__ Wo, const float* __restrict__ bo,
               float* __restrict__ out, int n, int ntiles)
{
    extern __shared__ char sm[];
    __half* wa_hi  = (__half*)(sm + O_WA_HI);
    __half* wa_lo  = (__half*)(sm + O_WA_LO);
    __half* wnh_hi = (__half*)(sm + O_WNH_HI);
    __half* wnh_lo = (__half*)(sm + O_WNH_LO);
    __half* wo_hi  = (__half*)(sm + O_WO_HI);
    __half* wo_lo  = (__half*)(sm + O_WO_LO);
    __half* Hh     = (__half*)(sm + O_H_HI);
    __half* Hl     = (__half*)(sm + O_H_LO);
    __half* xh     = (__half*)(sm + O_X_HI);
    __half* xl     = (__half*)(sm + O_X_LO);
    float*  A      = (float*)(sm + O_A);
    float*  nrnh   = (float*)(sm + O_NRNH);
    __half* nbh    = (__half*)(sm + O_NBR_HI);
    __half* nbl    = (__half*)(sm + O_NBR_LO);
    float*  sba    = (float*)(sm + O_BA);
    float*  sbo    = (float*)(sm + O_BO);
    float*  msk    = (float*)(sm + O_MSK);

    const int tid  = threadIdx.x;
    const int lane = tid & 31;
    const int w    = tid >> 5;

    // per-lane bias registers (cols 4*lane .. 4*lane+3 of 128)
    const float4 bn4 = *reinterpret_cast<const float4*>(bn + 4 * lane);
    const float4 bh4 = *reinterpret_cast<const float4*>(bh + 4 * lane);

    // ---- once per kernel: weights hi/lo split into padded SMEM ----
    for (int i = tid; i < 64 * 128; i += THREADS) {
        int k = i >> 7, c = i & 127;
        split16(Wa[i], wa_hi[k * LD_WA + c], wa_lo[k * LD_WA + c]);
    }
    for (int i = tid; i < 64 * 256; i += THREADS) {
        int k = i >> 8, c = i & 255;
        float x = (c < 128) ? Wn[k * 128 + c] : Wh[k * 128 + c - 128];
        split16(x, wnh_hi[k * LD_WNH + c], wnh_lo[k * LD_WNH + c]);
    }
    for (int i = tid; i < 128 * 64; i += THREADS) {
        int k = i >> 6, c = i & 63;
        split16(Wo[i], wo_hi[k * LD_WO + c], wo_lo[k * LD_WO + c]);
    }
    if (tid < 128) {
        sba[tid] = ba[tid];
        if (tid < 64) sbo[tid] = bo[tid];
    }
    __syncthreads();

    for (int tile = blockIdx.x; tile < ntiles; tile += gridDim.x) {
        const int base = tile * M_AG;

        // ---- prologue: X hi/lo, masks, neighbor chunk 0 ----
        for (int i = tid; i < 64 * 64; i += THREADS) {
            int r = i >> 6, c = i & 63;
            int ag = min(base + r, n - 1);
            split16(agent[(size_t)ag * 64 + c], xh[r * LD_X + c], xl[r * LD_X + c]);
        }
        {
            int ag = min(base + (tid >> 2), n - 1);
            msk[tid] = (float)nmask[(size_t)ag * 4 + (tid & 3)];
        }
        for (int i = tid; i < 16 * 64; i += THREADS) {
            int r = i >> 6, c = i & 63;
            int ag = min(base + (r >> 2), n - 1);
            float x = neighbor[((size_t)ag * 4 + (r & 3)) * 64 + c];
            split16(x, nbh[r * LD_X + c], nbl[r * LD_X + c]);
        }
        __syncthreads();

        // ---- GEMM1: A = X @ Wa  (64x128, K=64, fp16x3) ----
        {
            // per-warp column block nb = w is fixed -> preload B fragments
            frag_b bhf[4], blf[4];
#pragma unroll
            for (int k = 0; k < 4; ++k) {
                wmma::load_matrix_sync(bhf[k], wa_hi + k * 16 * LD_WA + w * 16, LD_WA);
                wmma::load_matrix_sync(blf[k], wa_lo + k * 16 * LD_WA + w * 16, LD_WA);
            }
#pragma unroll
            for (int rb = 0; rb < 4; ++rb) {
                frag_c acc;
                wmma::fill_fragment(acc, 0.f);
#pragma unroll
                for (int k = 0; k < 4; ++k) {
                    frag_a ahf, alf;
                    wmma::load_matrix_sync(ahf, xh + rb * 16 * LD_X + k * 16, LD_X);
                    wmma::load_matrix_sync(alf, xl + rb * 16 * LD_X + k * 16, LD_X);
                    wmma::mma_sync(acc, ahf, bhf[k], acc);
                    wmma::mma_sync(acc, ahf, blf[k], acc);
                    wmma::mma_sync(acc, alf, bhf[k], acc);
                }
                wmma::store_matrix_sync(A + rb * 16 * LD_A + w * 16, acc, LD_A,
                                        wmma::mem_row_major);
            }
        }
        __syncthreads();
        for (int i = tid; i < 64 * 128; i += THREADS) {
            int r = i >> 7, c = i & 127;
            A[r * LD_A + c] = fmaxf(A[r * LD_A + c] + sba[c], 0.f);
        }
        __syncthreads();

        // ---- neighbor chunks ----
        for (int c = 0; c < NCHUNK; ++c) {
            // warps 4-7: prefetch next chunk's gmem data into registers
            float pf[8];
            if (w >= 4 && c + 1 < NCHUNK) {
                const int t128 = tid - 128;
#pragma unroll
                for (int j = 0; j < 8; ++j) {
                    int i = t128 + j * 128;              // 0..1023
                    int r = i >> 6, cc = i & 63;
                    int ag = min(base + (c + 1) * 4 + (r >> 2), n - 1);
                    pf[j] = neighbor[((size_t)ag * 4 + (r & 3)) * 64 + cc];
                }
            }

            // GEMM2: NRNH = NBR @ (Wn|Wh)   (16x256, K=64, fp16x3)
            {
                frag_c acc0, acc1;
                wmma::fill_fragment(acc0, 0.f);
                wmma::fill_fragment(acc1, 0.f);
#pragma unroll
                for (int k = 0; k < 4; ++k) {
                    frag_a ahf, alf;
                    wmma::load_matrix_sync(ahf, nbh + k * 16, LD_X);
                    wmma::load_matrix_sync(alf, nbl + k * 16, LD_X);
                    frag_b bhf, blf;
                    wmma::load_matrix_sync(bhf, wnh_hi + k * 16 * LD_WNH + w * 16, LD_WNH);
                    wmma::load_matrix_sync(blf, wnh_lo + k * 16 * LD_WNH + w * 16, LD_WNH);
                    wmma::mma_sync(acc0, ahf, bhf, acc0);
                    wmma::mma_sync(acc0, ahf, blf, acc0);
                    wmma::mma_sync(acc0, alf, bhf, acc0);
                    wmma::load_matrix_sync(bhf, wnh_hi + k * 16 * LD_WNH + (w + 8) * 16, LD_WNH);
                    wmma::load_matrix_sync(blf, wnh_lo + k * 16 * LD_WNH + (w + 8) * 16, LD_WNH);
                    wmma::mma_sync(acc1, ahf, bhf, acc1);
                    wmma::mma_sync(acc1, ahf, blf, acc1);
                    wmma::mma_sync(acc1, alf, bhf, acc1);
                }
                wmma::store_matrix_sync(nrnh + w * 16, acc0, LD_NR, wmma::mem_row_major);
                wmma::store_matrix_sync(nrnh + (w + 8) * 16, acc1, LD_NR, wmma::mem_row_major);
            }
            __syncthreads();

            if (w < 4) {
                // ---- epilogue: agent a_t = 4c + w ----
                const int a_t = c * 4 + w;
                float4 av = *reinterpret_cast<const float4*>(A + a_t * LD_A + 4 * lane);
                float nr[4][4], nh[4][4], p[4];
#pragma unroll
                for (int nb_ = 0; nb_ < 4; ++nb_) {
                    const float* row = nrnh + (w * 4 + nb_) * LD_NR;
                    float4 rv = *reinterpret_cast<const float4*>(row + 4 * lane);
                    float4 hv = *reinterpret_cast<const float4*>(row + 128 + 4 * lane);
                    nr[nb_][0] = fmaxf(rv.x + bn4.x, 0.f);
                    nr[nb_][1] = fmaxf(rv.y + bn4.y, 0.f);
                    nr[nb_][2] = fmaxf(rv.z + bn4.z, 0.f);
                    nr[nb_][3] = fmaxf(rv.w + bn4.w, 0.f);
                    nh[nb_][0] = fmaxf(hv.x + bh4.x, 0.f);
                    nh[nb_][1] = fmaxf(hv.y + bh4.y, 0.f);
                    nh[nb_][2] = fmaxf(hv.z + bh4.z, 0.f);
                    nh[nb_][3] = fmaxf(hv.w + bh4.w, 0.f);
                    p[nb_] = av.x * nr[nb_][0] + av.y * nr[nb_][1] +
                             av.z * nr[nb_][2] + av.w * nr[nb_][3];
                }
#pragma unroll
                for (int off = 1; off < 8; off <<= 1)
#pragma unroll
                    for (int nb_ = 0; nb_ < 4; ++nb_)
                        p[nb_] += __shfl_xor_sync(0xffffffffu, p[nb_], off);

                float mk[4], lg[4];
#pragma unroll
                for (int nb_ = 0; nb_ < 4; ++nb_) {
                    mk[nb_] = msk[a_t * 4 + nb_];
                    lg[nb_] = fmaf(mk[nb_], -1e8f, p[nb_]);
                }
                float m = fmaxf(fmaxf(lg[0], lg[1]), fmaxf(lg[2], lg[3]));
                float e[4], s = 0.f;
#pragma unroll
                for (int nb_ = 0; nb_ < 4; ++nb_) { e[nb_] = __expf(lg[nb_] - m); s += e[nb_]; }
                float inv = 0.25f / s;
                float sc[4];
#pragma unroll
                for (int nb_ = 0; nb_ < 4; ++nb_) sc[nb_] = (1.f - mk[nb_]) * e[nb_] * inv;

                __half hhi[4], hlo[4];
#pragma unroll
                for (int t = 0; t < 4; ++t) {
                    float hv = sc[0] * nh[0][t] + sc[1] * nh[1][t] +
                               sc[2] * nh[2][t] + sc[3] * nh[3][t];
                    split16(hv, hhi[t], hlo[t]);
                }
                *reinterpret_cast<uint2*>(Hh + a_t * LD_H + 4 * lane) =
                    *reinterpret_cast<uint2*>(hhi);
                *reinterpret_cast<uint2*>(Hl + a_t * LD_H + 4 * lane) =
                    *reinterpret_cast<uint2*>(hlo);
            } else if (c + 1 < NCHUNK) {
                // warps 4-7: split + store prefetched NBR chunk
                const int t128 = tid - 128;
#pragma unroll
                for (int j = 0; j < 8; ++j) {
                    int i = t128 + j * 128;
                    int r = i >> 6, cc = i & 63;
                    split16(pf[j], nbh[r * LD_X + cc], nbl[r * LD_X + cc]);
                }
            }
            __syncthreads();
        }

        // ---- GEMM3: out = H @ Wo  (64x64, K=128, fp16x3) ----
        {
            const int nb = w & 3;
            const int rb0 = (w >> 2);       // rb0 and rb0+2
            frag_c acc0, acc1;
            wmma::fill_fragment(acc0, 0.f);
            wmma::fill_fragment(acc1, 0.f);
#pragma unroll
            for (int k = 0; k < 8; ++k) {
                frag_b bhf, blf;
                wmma::load_matrix_sync(bhf, wo_hi + k * 16 * LD_WO + nb * 16, LD_WO);
                wmma::load_matrix_sync(blf, wo_lo + k * 16 * LD_WO + nb * 16, LD_WO);
                frag_a ahf, alf;
                wmma::load_matrix_sync(ahf, Hh + rb0 * 16 * LD_H + k * 16, LD_H);
                wmma::load_matrix_sync(alf, Hl + rb0 * 16 * LD_H + k * 16, LD_H);
                wmma::mma_sync(acc0, ahf, bhf, acc0);
                wmma::mma_sync(acc0, ahf, blf, acc0);
                wmma::mma_sync(acc0, alf, bhf, acc0);
                wmma::load_matrix_sync(ahf, Hh + (rb0 + 2) * 16 * LD_H + k * 16, LD_H);
                wmma::load_matrix_sync(alf, Hl + (rb0 + 2) * 16 * LD_H + k * 16, LD_H);
                wmma::mma_sync(acc1, ahf, bhf, acc1);
                wmma::mma_sync(acc1, ahf, blf, acc1);
                wmma::mma_sync(acc1, alf, bhf, acc1);
            }
            wmma::store_matrix_sync(A + rb0 * 16 * LD_O + nb * 16, acc0, LD_O,
                                    wmma::mem_row_major);
            wmma::store_matrix_sync(A + (rb0 + 2) * 16 * LD_O + nb * 16, acc1, LD_O,
                                    wmma::mem_row_major);
        }
        __syncthreads();
        for (int i = tid; i < 64 * 64; i += THREADS) {
            int r = i >> 6, cc = i & 63;
            int ag = base + r;
            if (ag < n)
                out[(size_t)ag * 64 + cc] = fmaxf(A[r * LD_O + cc] + sbo[cc], 0.f);
        }
        __syncthreads();
    }
}

extern "C" void kernel_launch(void* const* d_in, const int* in_sizes, int n_in,
                              void* d_out, int out_size)
{
    const float* agent    = (const float*)d_in[0];
    const float* neighbor = (const float*)d_in[1];
    const int*   nmask    = (const int*)d_in[2];
    const float* Wa       = (const float*)d_in[3];
    const float* ba       = (const float*)d_in[4];
    const float* Wn       = (const float*)d_in[5];
    const float* bn       = (const float*)d_in[6];
    const float* Wh       = (const float*)d_in[7];
    const float* bh       = (const float*)d_in[8];
    const float* Wo       = (const float*)d_in[9];
    const float* bo       = (const float*)d_in[10];
    float* out = (float*)d_out;

    const int n = in_sizes[0] / 64;
    const int ntiles = (n + M_AG - 1) / M_AG;

    cudaFuncSetAttribute(gat_wmma2, cudaFuncAttributeMaxDynamicSharedMemorySize,
                         SMEM_TOTAL);

    int sms = 148;
    cudaDeviceGetAttribute(&sms, cudaDevAttrMultiProcessorCount, 0);
    int grid = sms < ntiles ? sms : ntiles;
    if (grid < 1) grid = 1;

    gat_wmma2<<<grid, THREADS, SMEM_TOTAL>>>(agent, neighbor, nmask,
                                             Wa, ba, Wn, bn, Wh, bh, Wo, bo,
                                             out, n, ntiles);
}

// round 6
// speedup vs baseline: 4.8997x; 1.2141x over previous
#include <cuda_runtime.h>
#include <cuda_fp16.h>
#include <cstdint>

#define THREADS 256

// ---- SMEM byte offsets ----
enum {
  O_WAT_HI  = 0,         // Wa^T  [128 n][72 k] half
  O_WAT_LO  = 18432,
  O_WNHT_HI = 36864,     // (Wn|Wh)^T [256 n][72 k] half (rows 0-127 Wn^T, 128-255 Wh^T)
  O_WNHT_LO = 73728,
  O_WOT_HI  = 110592,    // Wo^T  [64 n][136 k] half
  O_WOT_LO  = 128000,
  O_HH      = 145408,    // H hi  [64][136] half
  O_HL      = 162816,
  O_AS      = 180224,    // A f32 [64][132]
  O_BA      = 214016,    // f32[128]
  O_BN      = 214528,
  O_BH      = 215040,
  O_BO      = 215552,    // f32[64]
  O_MSK     = 215808,    // f32[256]
  SMEM_TOTAL = 216832
};

#define LD_WT  72   // halfs per row, K=64 weights
#define LD_WO  136  // halfs per row, K=128 weights / H
#define LD_AS  132  // floats per row

__device__ __forceinline__ void mma_f16(float* c, const uint32_t* a,
                                        uint32_t b0, uint32_t b1) {
    asm volatile(
        "mma.sync.aligned.m16n8k16.row.col.f32.f16.f16.f32 "
        "{%0,%1,%2,%3}, {%4,%5,%6,%7}, {%8,%9}, {%0,%1,%2,%3};\n"
        : "+f"(c[0]), "+f"(c[1]), "+f"(c[2]), "+f"(c[3])
        : "r"(a[0]), "r"(a[1]), "r"(a[2]), "r"(a[3]), "r"(b0), "r"(b1));
}

// split float2 into hi/lo packed half2 (elem0 in low 16 bits)
__device__ __forceinline__ void sp2(float2 v, uint32_t& h, uint32_t& l) {
    __half2 hh = __floats2half2_rn(v.x, v.y);
    __half2 ll = __floats2half2_rn(v.x - __low2float(hh), v.y - __high2float(hh));
    h = *reinterpret_cast<uint32_t*>(&hh);
    l = *reinterpret_cast<uint32_t*>(&ll);
}

__device__ __forceinline__ float relu(float x) { return fmaxf(x, 0.f); }

// load A-fragments (hi/lo) for one 16-row block from two gmem row pointers
// rows r_lo = g, r_hi = g+8 of the block; 4 k-tiles covering K=64
__device__ __forceinline__ void load_afrags(const float* rl, const float* rh,
                                            int q, uint32_t ah[4][4], uint32_t al[4][4]) {
#pragma unroll
    for (int kt = 0; kt < 4; ++kt) {
        int c0 = 16 * kt + 2 * q;
        sp2(*reinterpret_cast<const float2*>(rl + c0),     ah[kt][0], al[kt][0]);
        sp2(*reinterpret_cast<const float2*>(rh + c0),     ah[kt][1], al[kt][1]);
        sp2(*reinterpret_cast<const float2*>(rl + c0 + 8), ah[kt][2], al[kt][2]);
        sp2(*reinterpret_cast<const float2*>(rh + c0 + 8), ah[kt][3], al[kt][3]);
    }
}

__global__ __launch_bounds__(THREADS, 1)
void gat_mma(const float* __restrict__ agent,
             const float* __restrict__ neighbor,
             const int*   __restrict__ nmask,
             const float* __restrict__ Wa, const float* __restrict__ ba,
             const float* __restrict__ Wn, const float* __restrict__ bn,
             const float* __restrict__ Wh, const float* __restrict__ bh,
             const float* __restrict__ Wo, const float* __restrict__ bo,
             float* __restrict__ out, int n, int ntiles)
{
    extern __shared__ char sm[];
    __half* watH  = (__half*)(sm + O_WAT_HI);
    __half* watL  = (__half*)(sm + O_WAT_LO);
    __half* wnhH  = (__half*)(sm + O_WNHT_HI);
    __half* wnhL  = (__half*)(sm + O_WNHT_LO);
    __half* wotH  = (__half*)(sm + O_WOT_HI);
    __half* wotL  = (__half*)(sm + O_WOT_LO);
    __half* Hh    = (__half*)(sm + O_HH);
    __half* Hl    = (__half*)(sm + O_HL);
    float*  A_s   = (float*)(sm + O_AS);
    float*  sba   = (float*)(sm + O_BA);
    float*  sbn   = (float*)(sm + O_BN);
    float*  sbh   = (float*)(sm + O_BH);
    float*  sbo   = (float*)(sm + O_BO);
    float*  msk   = (float*)(sm + O_MSK);

    const int tid  = threadIdx.x;
    const int lane = tid & 31;
    const int w    = tid >> 5;
    const int g    = lane >> 2;   // group id (0..7)
    const int q    = lane & 3;    // thread in group

    // ---- once: transpose + split weights into SMEM ----
    for (int i = tid; i < 128 * 64; i += THREADS) {
        int nn = i >> 6, k = i & 63;
        float x = Wa[k * 128 + nn];
        __half hx = __float2half_rn(x);
        watH[nn * LD_WT + k] = hx;
        watL[nn * LD_WT + k] = __float2half_rn(x - __half2float(hx));
    }
    for (int i = tid; i < 256 * 64; i += THREADS) {
        int nn = i >> 6, k = i & 63;
        float x = (nn < 128) ? Wn[k * 128 + nn] : Wh[k * 128 + nn - 128];
        __half hx = __float2half_rn(x);
        wnhH[nn * LD_WT + k] = hx;
        wnhL[nn * LD_WT + k] = __float2half_rn(x - __half2float(hx));
    }
    for (int i = tid; i < 64 * 128; i += THREADS) {
        int nn = i >> 7, k = i & 127;
        float x = Wo[k * 64 + nn];
        __half hx = __float2half_rn(x);
        wotH[nn * LD_WO + k] = hx;
        wotL[nn * LD_WO + k] = __float2half_rn(x - __half2float(hx));
    }
    if (tid < 128) {
        sba[tid] = ba[tid]; sbn[tid] = bn[tid]; sbh[tid] = bh[tid];
        if (tid < 64) sbo[tid] = bo[tid];
    }
    __syncthreads();

    for (int tile = blockIdx.x; tile < ntiles; tile += gridDim.x) {
        const int base = tile * 64;

        // masks
        {
            int ag = min(base + (tid >> 2), n - 1);
            msk[tid] = (float)nmask[(size_t)ag * 4 + (tid & 3)];
        }

        // ---- GEMM1: A_s = relu(X @ Wa + ba)  [64 x 128], K=64 ----
        {
            const int rb = w & 3;
            const int nh0 = (w >> 2) * 64;
            uint32_t ah[4][4], al[4][4];
            int rlo = min(base + rb * 16 + g,     n - 1);
            int rhi = min(base + rb * 16 + g + 8, n - 1);
            load_afrags(agent + (size_t)rlo * 64, agent + (size_t)rhi * 64, q, ah, al);
#pragma unroll
            for (int nt = 0; nt < 8; ++nt) {
                float c[4] = {0.f, 0.f, 0.f, 0.f};
                const __half* bhp = watH + (nh0 + nt * 8 + g) * LD_WT;
                const __half* blp = watL + (nh0 + nt * 8 + g) * LD_WT;
#pragma unroll
                for (int kt = 0; kt < 4; ++kt) {
                    int k0 = 16 * kt + 2 * q;
                    uint32_t b0 = *reinterpret_cast<const uint32_t*>(bhp + k0);
                    uint32_t b1 = *reinterpret_cast<const uint32_t*>(bhp + k0 + 8);
                    uint32_t c0l = *reinterpret_cast<const uint32_t*>(blp + k0);
                    uint32_t c1l = *reinterpret_cast<const uint32_t*>(blp + k0 + 8);
                    mma_f16(c, ah[kt], b0, b1);
                    mma_f16(c, ah[kt], c0l, c1l);
                    mma_f16(c, al[kt], b0, b1);
                }
                int colc = nh0 + nt * 8 + 2 * q;
                float2 bav = *reinterpret_cast<const float2*>(sba + colc);
                float* d0 = A_s + (rb * 16 + g) * LD_AS + colc;
                float* d1 = A_s + (rb * 16 + g + 8) * LD_AS + colc;
                d0[0] = relu(c[0] + bav.x); d0[1] = relu(c[1] + bav.y);
                d1[0] = relu(c[2] + bav.x); d1[1] = relu(c[3] + bav.y);
            }
        }
        __syncthreads();

        // ---- GEMM2 + attention epilogue: 2 blocks of 16 neighbor rows per warp ----
#pragma unroll 1
        for (int bi = 0; bi < 2; ++bi) {
            const int blk = w + 8 * bi;          // 0..15, 4 agents each
            const int a_lo = blk * 4 + (g >> 2);       // agent of row g
            const int a_hi = a_lo + 2;                 // agent of row g+8
            int agl = min(base + a_lo, n - 1);
            int agh = min(base + a_hi, n - 1);
            uint32_t ah[4][4], al[4][4];
            load_afrags(neighbor + ((size_t)agl * 4 + (g & 3)) * 64,
                        neighbor + ((size_t)agh * 4 + (g & 3)) * 64, q, ah, al);

            const float mk_lo = msk[blk * 16 + g];
            const float mk_hi = msk[blk * 16 + g + 8];
            const float* arow_lo = A_s + a_lo * LD_AS;
            const float* arow_hi = A_s + a_hi * LD_AS;

#pragma unroll 1
            for (int h = 0; h < 4; ++h) {
                float c[4][4] = {};
                // --- nr GEMM: rows 32h.. of Wn^T ---
#pragma unroll
                for (int kt = 0; kt < 4; ++kt) {
                    int k0 = 16 * kt + 2 * q;
#pragma unroll
                    for (int nt = 0; nt < 4; ++nt) {
                        const __half* bhp = wnhH + (32 * h + 8 * nt + g) * LD_WT + k0;
                        const __half* blp = wnhL + (32 * h + 8 * nt + g) * LD_WT + k0;
                        uint32_t b0 = *reinterpret_cast<const uint32_t*>(bhp);
                        uint32_t b1 = *reinterpret_cast<const uint32_t*>(bhp + 8);
                        uint32_t l0 = *reinterpret_cast<const uint32_t*>(blp);
                        uint32_t l1 = *reinterpret_cast<const uint32_t*>(blp + 8);
                        mma_f16(c[nt], ah[kt], b0, b1);
                        mma_f16(c[nt], ah[kt], l0, l1);
                        mma_f16(c[nt], al[kt], b0, b1);
                    }
                }
                // --- attention logits ---
                float p_lo = 0.f, p_hi = 0.f;
#pragma unroll
                for (int nt = 0; nt < 4; ++nt) {
                    int colc = 32 * h + 8 * nt + 2 * q;
                    float2 bnv = *reinterpret_cast<const float2*>(sbn + colc);
                    float e0 = relu(c[nt][0] + bnv.x), e1 = relu(c[nt][1] + bnv.y);
                    float e2 = relu(c[nt][2] + bnv.x), e3 = relu(c[nt][3] + bnv.y);
                    float2 avl = *reinterpret_cast<const float2*>(arow_lo + colc);
                    float2 avh = *reinterpret_cast<const float2*>(arow_hi + colc);
                    p_lo = fmaf(e0, avl.x, fmaf(e1, avl.y, p_lo));
                    p_hi = fmaf(e2, avh.x, fmaf(e3, avh.y, p_hi));
                }
                p_lo += __shfl_xor_sync(0xffffffffu, p_lo, 1);
                p_lo += __shfl_xor_sync(0xffffffffu, p_lo, 2);
                p_hi += __shfl_xor_sync(0xffffffffu, p_hi, 1);
                p_hi += __shfl_xor_sync(0xffffffffu, p_hi, 2);
                // --- softmax over the agent's 4 rows (groups via xor 4,8) ---
                float lg_lo = fmaf(mk_lo, -1e8f, p_lo);
                float lg_hi = fmaf(mk_hi, -1e8f, p_hi);
                float m_lo = lg_lo, m_hi = lg_hi;
                m_lo = fmaxf(m_lo, __shfl_xor_sync(0xffffffffu, m_lo, 4));
                m_lo = fmaxf(m_lo, __shfl_xor_sync(0xffffffffu, m_lo, 8));
                m_hi = fmaxf(m_hi, __shfl_xor_sync(0xffffffffu, m_hi, 4));
                m_hi = fmaxf(m_hi, __shfl_xor_sync(0xffffffffu, m_hi, 8));
                float e_lo = __expf(lg_lo - m_lo), e_hi = __expf(lg_hi - m_hi);
                float s_lo = e_lo, s_hi = e_hi;
                s_lo += __shfl_xor_sync(0xffffffffu, s_lo, 4);
                s_lo += __shfl_xor_sync(0xffffffffu, s_lo, 8);
                s_hi += __shfl_xor_sync(0xffffffffu, s_hi, 4);
                s_hi += __shfl_xor_sync(0xffffffffu, s_hi, 8);
                float sc_lo = (1.f - mk_lo) * e_lo * 0.25f / s_lo;
                float sc_hi = (1.f - mk_hi) * e_hi * 0.25f / s_hi;

                // --- nh GEMM: rows 128+32h.. of Wh^T ---
#pragma unroll
                for (int nt = 0; nt < 4; ++nt) {
                    c[nt][0] = c[nt][1] = c[nt][2] = c[nt][3] = 0.f;
                }
#pragma unroll
                for (int kt = 0; kt < 4; ++kt) {
                    int k0 = 16 * kt + 2 * q;
#pragma unroll
                    for (int nt = 0; nt < 4; ++nt) {
                        const __half* bhp = wnhH + (128 + 32 * h + 8 * nt + g) * LD_WT + k0;
                        const __half* blp = wnhL + (128 + 32 * h + 8 * nt + g) * LD_WT + k0;
                        uint32_t b0 = *reinterpret_cast<const uint32_t*>(bhp);
                        uint32_t b1 = *reinterpret_cast<const uint32_t*>(bhp + 8);
                        uint32_t l0 = *reinterpret_cast<const uint32_t*>(blp);
                        uint32_t l1 = *reinterpret_cast<const uint32_t*>(blp + 8);
                        mma_f16(c[nt], ah[kt], b0, b1);
                        mma_f16(c[nt], ah[kt], l0, l1);
                        mma_f16(c[nt], al[kt], b0, b1);
                    }
                }
                // --- weighted mean -> H (hi/lo fp16) ---
#pragma unroll
                for (int nt = 0; nt < 4; ++nt) {
                    int colc = 32 * h + 8 * nt + 2 * q;
                    float2 bhv = *reinterpret_cast<const float2*>(sbh + colc);
                    float f0 = relu(c[nt][0] + bhv.x) * sc_lo;
                    float f1 = relu(c[nt][1] + bhv.y) * sc_lo;
                    float f2 = relu(c[nt][2] + bhv.x) * sc_hi;
                    float f3 = relu(c[nt][3] + bhv.y) * sc_hi;
                    f0 += __shfl_xor_sync(0xffffffffu, f0, 4);
                    f0 += __shfl_xor_sync(0xffffffffu, f0, 8);
                    f1 += __shfl_xor_sync(0xffffffffu, f1, 4);
                    f1 += __shfl_xor_sync(0xffffffffu, f1, 8);
                    f2 += __shfl_xor_sync(0xffffffffu, f2, 4);
                    f2 += __shfl_xor_sync(0xffffffffu, f2, 8);
                    f3 += __shfl_xor_sync(0xffffffffu, f3, 4);
                    f3 += __shfl_xor_sync(0xffffffffu, f3, 8);
                    if ((g & 3) == 0) {
                        uint32_t hp, lp;
                        sp2(make_float2(f0, f1), hp, lp);
                        *reinterpret_cast<uint32_t*>(Hh + a_lo * LD_WO + colc) = hp;
                        *reinterpret_cast<uint32_t*>(Hl + a_lo * LD_WO + colc) = lp;
                        sp2(make_float2(f2, f3), hp, lp);
                        *reinterpret_cast<uint32_t*>(Hh + a_hi * LD_WO + colc) = hp;
                        *reinterpret_cast<uint32_t*>(Hl + a_hi * LD_WO + colc) = lp;
                    }
                }
            }
        }
        __syncthreads();

        // ---- GEMM3: out = relu(H @ Wo + bo)  [64 x 64], K=128 ----
        {
            const int rb = w & 3;
            const int nh0 = (w >> 2) * 32;
            float c[4][4] = {};
#pragma unroll
            for (int kt = 0; kt < 8; ++kt) {
                int k0 = 16 * kt + 2 * q;
                uint32_t ah[4], al[4];
                const __half* hl = Hh + (rb * 16 + g) * LD_WO + k0;
                const __half* hu = Hh + (rb * 16 + g + 8) * LD_WO + k0;
                const __half* ll = Hl + (rb * 16 + g) * LD_WO + k0;
                const __half* lu = Hl + (rb * 16 + g + 8) * LD_WO + k0;
                ah[0] = *reinterpret_cast<const uint32_t*>(hl);
                ah[1] = *reinterpret_cast<const uint32_t*>(hu);
                ah[2] = *reinterpret_cast<const uint32_t*>(hl + 8);
                ah[3] = *reinterpret_cast<const uint32_t*>(hu + 8);
                al[0] = *reinterpret_cast<const uint32_t*>(ll);
                al[1] = *reinterpret_cast<const uint32_t*>(lu);
                al[2] = *reinterpret_cast<const uint32_t*>(ll + 8);
                al[3] = *reinterpret_cast<const uint32_t*>(lu + 8);
#pragma unroll
                for (int nt = 0; nt < 4; ++nt) {
                    const __half* bhp = wotH + (nh0 + 8 * nt + g) * LD_WO + k0;
                    const __half* blp = wotL + (nh0 + 8 * nt + g) * LD_WO + k0;
                    uint32_t b0 = *reinterpret_cast<const uint32_t*>(bhp);
                    uint32_t b1 = *reinterpret_cast<const uint32_t*>(bhp + 8);
                    uint32_t l0 = *reinterpret_cast<const uint32_t*>(blp);
                    uint32_t l1 = *reinterpret_cast<const uint32_t*>(blp + 8);
                    mma_f16(c[nt], ah, b0, b1);
                    mma_f16(c[nt], ah, l0, l1);
                    mma_f16(c[nt], al, b0, b1);
                }
            }
            int rlo = base + rb * 16 + g;
            int rhi = rlo + 8;
#pragma unroll
            for (int nt = 0; nt < 4; ++nt) {
                int colc = nh0 + 8 * nt + 2 * q;
                float2 bov = *reinterpret_cast<const float2*>(sbo + colc);
                if (rlo < n) {
                    float2 v = make_float2(relu(c[nt][0] + bov.x),
                                           relu(c[nt][1] + bov.y));
                    *reinterpret_cast<float2*>(out + (size_t)rlo * 64 + colc) = v;
                }
                if (rhi < n) {
                    float2 v = make_float2(relu(c[nt][2] + bov.x),
                                           relu(c[nt][3] + bov.y));
                    *reinterpret_cast<float2*>(out + (size_t)rhi * 64 + colc) = v;
                }
            }
        }
        __syncthreads();
    }
}

extern "C" void kernel_launch(void* const* d_in, const int* in_sizes, int n_in,
                              void* d_out, int out_size)
{
    const float* agent    = (const float*)d_in[0];
    const float* neighbor = (const float*)d_in[1];
    const int*   nmask    = (const int*)d_in[2];
    const float* Wa       = (const float*)d_in[3];
    const float* ba       = (const float*)d_in[4];
    const float* Wn       = (const float*)d_in[5];
    const float* bn       = (const float*)d_in[6];
    const float* Wh       = (const float*)d_in[7];
    const float* bh       = (const float*)d_in[8];
    const float* Wo       = (const float*)d_in[9];
    const float* bo       = (const float*)d_in[10];
    float* out = (float*)d_out;

    const int n = in_sizes[0] / 64;
    const int ntiles = (n + 63) / 64;

    cudaFuncSetAttribute(gat_mma, cudaFuncAttributeMaxDynamicSharedMemorySize,
                         SMEM_TOTAL);

    int sms = 148;
    cudaDeviceGetAttribute(&sms, cudaDevAttrMultiProcessorCount, 0);
    int grid = sms < ntiles ? sms : ntiles;
    if (grid < 1) grid = 1;

    gat_mma<<<grid, THREADS, SMEM_TOTAL>>>(agent, neighbor, nmask,
                                           Wa, ba, Wn, bn, Wh, bh, Wo, bo,
                                           out, n, ntiles);
}

// round 7
// speedup vs baseline: 6.0227x; 1.2292x over previous
#include <cuda_runtime.h>
#include <cuda_fp16.h>
#include <cstdint>

#define THREADS 512

// ---- SMEM byte offsets ----
enum {
  O_FWA  = 0,        // GEMM1 B frags: uint4[16 nblk][4 kt][32 lane]  (32 KB)
  O_FWNH = 32768,    // GEMM2 B frags: uint4[32 nblk][4 kt][32 lane]  (64 KB)
  O_FWO  = 98304,    // GEMM3 B frags: uint4[8 nblk][8 kt][32 lane]   (32 KB)
  O_HH   = 131072,   // H hi [64][136] half
  O_HL   = 148480,
  O_AS   = 165888,   // A f32 [64][132]
  O_BA   = 199680,   // f32[128]
  O_BN   = 200192,
  O_BH   = 200704,
  O_BO   = 201216,   // f32[64]
  O_MSK  = 201472,   // f32[256]
  SMEM_TOTAL = 202496
};

#define LD_H   136  // halfs per row of H
#define LD_AS  132  // floats per row of A_s

__device__ __forceinline__ void mma_f16(float* c, const uint32_t* a,
                                        uint32_t b0, uint32_t b1) {
    asm volatile(
        "mma.sync.aligned.m16n8k16.row.col.f32.f16.f16.f32 "
        "{%0,%1,%2,%3}, {%4,%5,%6,%7}, {%8,%9}, {%0,%1,%2,%3};\n"
        : "+f"(c[0]), "+f"(c[1]), "+f"(c[2]), "+f"(c[3])
        : "r"(a[0]), "r"(a[1]), "r"(a[2]), "r"(a[3]), "r"(b0), "r"(b1));
}

__device__ __forceinline__ void sp2(float2 v, uint32_t& h, uint32_t& l) {
    __half2 hh = __floats2half2_rn(v.x, v.y);
    __half2 ll = __floats2half2_rn(v.x - __low2float(hh), v.y - __high2float(hh));
    h = *reinterpret_cast<uint32_t*>(&hh);
    l = *reinterpret_cast<uint32_t*>(&ll);
}

__device__ __forceinline__ float relu(float x) { return fmaxf(x, 0.f); }

// pack 4 weight values (k0,k0+1,k0+8,k0+9 of one n-col) into a B fragment uint4
__device__ __forceinline__ uint4 pack4(float w0, float w1, float w2, float w3) {
    __half2 h01 = __floats2half2_rn(w0, w1);
    __half2 h23 = __floats2half2_rn(w2, w3);
    __half2 l01 = __floats2half2_rn(w0 - __low2float(h01), w1 - __high2float(h01));
    __half2 l23 = __floats2half2_rn(w2 - __low2float(h23), w3 - __high2float(h23));
    uint4 r;
    r.x = *reinterpret_cast<uint32_t*>(&h01);
    r.y = *reinterpret_cast<uint32_t*>(&h23);
    r.z = *reinterpret_cast<uint32_t*>(&l01);
    r.w = *reinterpret_cast<uint32_t*>(&l23);
    return r;
}

// A-fragments (hi/lo) for one 16-row block from two gmem/smem f32 row pointers
__device__ __forceinline__ void load_afrags(const float* rl, const float* rh,
                                            int q, uint32_t ah[4][4], uint32_t al[4][4]) {
#pragma unroll
    for (int kt = 0; kt < 4; ++kt) {
        int c0 = 16 * kt + 2 * q;
        sp2(*reinterpret_cast<const float2*>(rl + c0),     ah[kt][0], al[kt][0]);
        sp2(*reinterpret_cast<const float2*>(rh + c0),     ah[kt][1], al[kt][1]);
        sp2(*reinterpret_cast<const float2*>(rl + c0 + 8), ah[kt][2], al[kt][2]);
        sp2(*reinterpret_cast<const float2*>(rh + c0 + 8), ah[kt][3], al[kt][3]);
    }
}

__global__ __launch_bounds__(THREADS, 1)
void gat_mma3(const float* __restrict__ agent,
              const float* __restrict__ neighbor,
              const int*   __restrict__ nmask,
              const float* __restrict__ Wa, const float* __restrict__ ba,
              const float* __restrict__ Wn, const float* __restrict__ bn,
              const float* __restrict__ Wh, const float* __restrict__ bh,
              const float* __restrict__ Wo, const float* __restrict__ bo,
              float* __restrict__ out, int n, int ntiles)
{
    extern __shared__ char sm[];
    uint4*  fWA  = (uint4*)(sm + O_FWA);
    uint4*  fWNH = (uint4*)(sm + O_FWNH);
    uint4*  fWO  = (uint4*)(sm + O_FWO);
    __half* Hh   = (__half*)(sm + O_HH);
    __half* Hl   = (__half*)(sm + O_HL);
    float*  A_s  = (float*)(sm + O_AS);
    float*  sba  = (float*)(sm + O_BA);
    float*  sbn  = (float*)(sm + O_BN);
    float*  sbh  = (float*)(sm + O_BH);
    float*  sbo  = (float*)(sm + O_BO);
    float*  msk  = (float*)(sm + O_MSK);

    const int tid  = threadIdx.x;
    const int lane = tid & 31;
    const int w    = tid >> 5;
    const int g    = lane >> 2;
    const int q    = lane & 3;

    // ---- once: pack weights into fragment-ready SMEM ----
    for (int i = tid; i < 2048; i += THREADS) {          // Wa^T: 16 nblk x 4 kt
        int li = i & 31, kt = (i >> 5) & 3, nb = i >> 7;
        int nn = nb * 8 + (li >> 2), k0 = kt * 16 + 2 * (li & 3);
        fWA[i] = pack4(Wa[k0 * 128 + nn], Wa[(k0 + 1) * 128 + nn],
                       Wa[(k0 + 8) * 128 + nn], Wa[(k0 + 9) * 128 + nn]);
    }
    for (int i = tid; i < 4096; i += THREADS) {          // (Wn|Wh)^T: 32 nblk x 4 kt
        int li = i & 31, kt = (i >> 5) & 3, nb = i >> 7;
        int nn = nb * 8 + (li >> 2), k0 = kt * 16 + 2 * (li & 3);
        const float* Wsrc = (nn < 128) ? Wn : Wh;
        int nc = (nn < 128) ? nn : nn - 128;
        fWNH[i] = pack4(Wsrc[k0 * 128 + nc], Wsrc[(k0 + 1) * 128 + nc],
                        Wsrc[(k0 + 8) * 128 + nc], Wsrc[(k0 + 9) * 128 + nc]);
    }
    for (int i = tid; i < 2048; i += THREADS) {          // Wo^T: 8 nblk x 8 kt
        int li = i & 31, kt = (i >> 5) & 7, nb = i >> 8;
        int nn = nb * 8 + (li >> 2), k0 = kt * 16 + 2 * (li & 3);
        fWO[i] = pack4(Wo[k0 * 64 + nn], Wo[(k0 + 1) * 64 + nn],
                       Wo[(k0 + 8) * 64 + nn], Wo[(k0 + 9) * 64 + nn]);
    }
    if (tid < 128) {
        sba[tid] = ba[tid]; sbn[tid] = bn[tid]; sbh[tid] = bh[tid];
        if (tid < 64) sbo[tid] = bo[tid];
    }
    __syncthreads();

    for (int tile = blockIdx.x; tile < ntiles; tile += gridDim.x) {
        const int base = tile * 64;

        if (tid < 256) {
            int ag = min(base + (tid >> 2), n - 1);
            msk[tid] = (float)nmask[(size_t)ag * 4 + (tid & 3)];
        }

        // ---- GEMM1: A_s = relu(X @ Wa + ba)  [64 x 128], K=64 ----
        {
            const int rb = w & 3, cs = w >> 2;           // rows rb*16.., cols cs*32..
            uint32_t ah[4][4], al[4][4];
            int rlo = min(base + rb * 16 + g,     n - 1);
            int rhi = min(base + rb * 16 + g + 8, n - 1);
            load_afrags(agent + (size_t)rlo * 64, agent + (size_t)rhi * 64, q, ah, al);
#pragma unroll
            for (int nt = 0; nt < 4; ++nt) {
                float c[4] = {0.f, 0.f, 0.f, 0.f};
                const int nb = cs * 4 + nt;
#pragma unroll
                for (int kt = 0; kt < 4; ++kt) {
                    uint4 B = fWA[(nb * 4 + kt) * 32 + lane];
                    mma_f16(c, ah[kt], B.x, B.y);
                    mma_f16(c, ah[kt], B.z, B.w);
                    mma_f16(c, al[kt], B.x, B.y);
                }
                int colc = cs * 32 + nt * 8 + 2 * q;
                float2 bav = *reinterpret_cast<const float2*>(sba + colc);
                float* d0 = A_s + (rb * 16 + g) * LD_AS + colc;
                float* d1 = A_s + (rb * 16 + g + 8) * LD_AS + colc;
                d0[0] = relu(c[0] + bav.x); d0[1] = relu(c[1] + bav.y);
                d1[0] = relu(c[2] + bav.x); d1[1] = relu(c[3] + bav.y);
            }
        }
        __syncthreads();

        // ---- GEMM2 + attention epilogue: one 16-row block per warp ----
        {
            const int blk  = w;                  // 4 agents
            const int a_lo = blk * 4 + (g >> 2);
            const int a_hi = a_lo + 2;
            int agl = min(base + a_lo, n - 1);
            int agh = min(base + a_hi, n - 1);
            uint32_t ah[4][4], al[4][4];
            load_afrags(neighbor + ((size_t)agl * 4 + (g & 3)) * 64,
                        neighbor + ((size_t)agh * 4 + (g & 3)) * 64, q, ah, al);

            const float mk_lo = msk[blk * 16 + g];
            const float mk_hi = msk[blk * 16 + g + 8];
            const float* arow_lo = A_s + a_lo * LD_AS;
            const float* arow_hi = A_s + a_hi * LD_AS;

#pragma unroll 1
            for (int h = 0; h < 4; ++h) {
                float c[4][4] = {};
                // --- nr GEMM (nblk = 4h+nt) ---
#pragma unroll
                for (int kt = 0; kt < 4; ++kt) {
#pragma unroll
                    for (int nt = 0; nt < 4; ++nt) {
                        uint4 B = fWNH[((4 * h + nt) * 4 + kt) * 32 + lane];
                        mma_f16(c[nt], ah[kt], B.x, B.y);
                        mma_f16(c[nt], ah[kt], B.z, B.w);
                        mma_f16(c[nt], al[kt], B.x, B.y);
                    }
                }
                // --- attention logits ---
                float p_lo = 0.f, p_hi = 0.f;
#pragma unroll
                for (int nt = 0; nt < 4; ++nt) {
                    int colc = 32 * h + 8 * nt + 2 * q;
                    float2 bnv = *reinterpret_cast<const float2*>(sbn + colc);
                    float e0 = relu(c[nt][0] + bnv.x), e1 = relu(c[nt][1] + bnv.y);
                    float e2 = relu(c[nt][2] + bnv.x), e3 = relu(c[nt][3] + bnv.y);
                    float2 avl = *reinterpret_cast<const float2*>(arow_lo + colc);
                    float2 avh = *reinterpret_cast<const float2*>(arow_hi + colc);
                    p_lo = fmaf(e0, avl.x, fmaf(e1, avl.y, p_lo));
                    p_hi = fmaf(e2, avh.x, fmaf(e3, avh.y, p_hi));
                }
                p_lo += __shfl_xor_sync(0xffffffffu, p_lo, 1);
                p_lo += __shfl_xor_sync(0xffffffffu, p_lo, 2);
                p_hi += __shfl_xor_sync(0xffffffffu, p_hi, 1);
                p_hi += __shfl_xor_sync(0xffffffffu, p_hi, 2);
                // --- softmax over 4 neighbor rows (lane bits 2,3) ---
                float lg_lo = fmaf(mk_lo, -1e8f, p_lo);
                float lg_hi = fmaf(mk_hi, -1e8f, p_hi);
                float m_lo = lg_lo, m_hi = lg_hi;
                m_lo = fmaxf(m_lo, __shfl_xor_sync(0xffffffffu, m_lo, 4));
                m_lo = fmaxf(m_lo, __shfl_xor_sync(0xffffffffu, m_lo, 8));
                m_hi = fmaxf(m_hi, __shfl_xor_sync(0xffffffffu, m_hi, 4));
                m_hi = fmaxf(m_hi, __shfl_xor_sync(0xffffffffu, m_hi, 8));
                float e_lo = __expf(lg_lo - m_lo), e_hi = __expf(lg_hi - m_hi);
                float s_lo = e_lo, s_hi = e_hi;
                s_lo += __shfl_xor_sync(0xffffffffu, s_lo, 4);
                s_lo += __shfl_xor_sync(0xffffffffu, s_lo, 8);
                s_hi += __shfl_xor_sync(0xffffffffu, s_hi, 4);
                s_hi += __shfl_xor_sync(0xffffffffu, s_hi, 8);
                float sc_lo = (1.f - mk_lo) * e_lo * 0.25f / s_lo;
                float sc_hi = (1.f - mk_hi) * e_hi * 0.25f / s_hi;

                // --- nh GEMM (nblk = 16+4h+nt) ---
#pragma unroll
                for (int nt = 0; nt < 4; ++nt)
                    c[nt][0] = c[nt][1] = c[nt][2] = c[nt][3] = 0.f;
#pragma unroll
                for (int kt = 0; kt < 4; ++kt) {
#pragma unroll
                    for (int nt = 0; nt < 4; ++nt) {
                        uint4 B = fWNH[((16 + 4 * h + nt) * 4 + kt) * 32 + lane];
                        mma_f16(c[nt], ah[kt], B.x, B.y);
                        mma_f16(c[nt], ah[kt], B.z, B.w);
                        mma_f16(c[nt], al[kt], B.x, B.y);
                    }
                }
                // --- weighted mean -> H ---
#pragma unroll
                for (int nt = 0; nt < 4; ++nt) {
                    int colc = 32 * h + 8 * nt + 2 * q;
                    float2 bhv = *reinterpret_cast<const float2*>(sbh + colc);
                    float f0 = relu(c[nt][0] + bhv.x) * sc_lo;
                    float f1 = relu(c[nt][1] + bhv.y) * sc_lo;
                    float f2 = relu(c[nt][2] + bhv.x) * sc_hi;
                    float f3 = relu(c[nt][3] + bhv.y) * sc_hi;
                    f0 += __shfl_xor_sync(0xffffffffu, f0, 4);
                    f0 += __shfl_xor_sync(0xffffffffu, f0, 8);
                    f1 += __shfl_xor_sync(0xffffffffu, f1, 4);
                    f1 += __shfl_xor_sync(0xffffffffu, f1, 8);
                    f2 += __shfl_xor_sync(0xffffffffu, f2, 4);
                    f2 += __shfl_xor_sync(0xffffffffu, f2, 8);
                    f3 += __shfl_xor_sync(0xffffffffu, f3, 4);
                    f3 += __shfl_xor_sync(0xffffffffu, f3, 8);
                    if ((g & 3) == 0) {
                        uint32_t hp, lp;
                        sp2(make_float2(f0, f1), hp, lp);
                        *reinterpret_cast<uint32_t*>(Hh + a_lo * LD_H + colc) = hp;
                        *reinterpret_cast<uint32_t*>(Hl + a_lo * LD_H + colc) = lp;
                        sp2(make_float2(f2, f3), hp, lp);
                        *reinterpret_cast<uint32_t*>(Hh + a_hi * LD_H + colc) = hp;
                        *reinterpret_cast<uint32_t*>(Hl + a_hi * LD_H + colc) = lp;
                    }
                }
            }
        }
        __syncthreads();

        // ---- GEMM3: out = relu(H @ Wo + bo)  [64 x 64], K=128 ----
        {
            const int rb = w & 3, cs = w >> 2;           // cols cs*16..
            float c[2][4] = {};
#pragma unroll
            for (int kt = 0; kt < 8; ++kt) {
                int k0 = 16 * kt + 2 * q;
                uint32_t ah[4], al[4];
                const __half* hl = Hh + (rb * 16 + g) * LD_H + k0;
                const __half* hu = Hh + (rb * 16 + g + 8) * LD_H + k0;
                const __half* ll = Hl + (rb * 16 + g) * LD_H + k0;
                const __half* lu = Hl + (rb * 16 + g + 8) * LD_H + k0;
                ah[0] = *reinterpret_cast<const uint32_t*>(hl);
                ah[1] = *reinterpret_cast<const uint32_t*>(hu);
                ah[2] = *reinterpret_cast<const uint32_t*>(hl + 8);
                ah[3] = *reinterpret_cast<const uint32_t*>(hu + 8);
                al[0] = *reinterpret_cast<const uint32_t*>(ll);
                al[1] = *reinterpret_cast<const uint32_t*>(lu);
                al[2] = *reinterpret_cast<const uint32_t*>(ll + 8);
                al[3] = *reinterpret_cast<const uint32_t*>(lu + 8);
#pragma unroll
                for (int nt = 0; nt < 2; ++nt) {
                    uint4 B = fWO[((cs * 2 + nt) * 8 + kt) * 32 + lane];
                    mma_f16(c[nt], ah, B.x, B.y);
                    mma_f16(c[nt], ah, B.z, B.w);
                    mma_f16(c[nt], al, B.x, B.y);
                }
            }
            int rlo = base + rb * 16 + g;
            int rhi = rlo + 8;
#pragma unroll
            for (int nt = 0; nt < 2; ++nt) {
                int colc = cs * 16 + nt * 8 + 2 * q;
                float2 bov = *reinterpret_cast<const float2*>(sbo + colc);
                if (rlo < n) {
                    float2 v = make_float2(relu(c[nt][0] + bov.x),
                                           relu(c[nt][1] + bov.y));
                    *reinterpret_cast<float2*>(out + (size_t)rlo * 64 + colc) = v;
                }
                if (rhi < n) {
                    float2 v = make_float2(relu(c[nt][2] + bov.x),
                                           relu(c[nt][3] + bov.y));
                    *reinterpret_cast<float2*>(out + (size_t)rhi * 64 + colc) = v;
                }
            }
        }
        __syncthreads();
    }
}

extern "C" void kernel_launch(void* const* d_in, const int* in_sizes, int n_in,
                              void* d_out, int out_size)
{
    const float* agent    = (const float*)d_in[0];
    const float* neighbor = (const float*)d_in[1];
    const int*   nmask    = (const int*)d_in[2];
    const float* Wa       = (const float*)d_in[3];
    const float* ba       = (const float*)d_in[4];
    const float* Wn       = (const float*)d_in[5];
    const float* bn       = (const float*)d_in[6];
    const float* Wh       = (const float*)d_in[7];
    const float* bh       = (const float*)d_in[8];
    const float* Wo       = (const float*)d_in[9];
    const float* bo       = (const float*)d_in[10];
    float* out = (float*)d_out;

    const int n = in_sizes[0] / 64;
    const int ntiles = (n + 63) / 64;

    cudaFuncSetAttribute(gat_mma3, cudaFuncAttributeMaxDynamicSharedMemorySize,
                         SMEM_TOTAL);

    int sms = 148;
    cudaDeviceGetAttribute(&sms, cudaDevAttrMultiProcessorCount, 0);
    int grid = sms < ntiles ? sms : ntiles;
    if (grid < 1) grid = 1;

    gat_mma3<<<grid, THREADS, SMEM_TOTAL>>>(agent, neighbor, nmask,
                                            Wa, ba, Wn, bn, Wh, bh, Wo, bo,
                                            out, n, ntiles);
}